// round 1
// baseline (speedup 1.0000x reference)
#include <cuda_runtime.h>

#define B   8
#define CI  32
#define CO  32
#define NY  128
#define NX  128
#define M1  4
#define M2  5

#define TWO_PI_F 6.283185307179586476925f

__device__ __forceinline__ float2 cmul(float2 a, float2 b) {
    return make_float2(a.x*b.x - a.y*b.y, a.x*b.y + a.y*b.x);
}
__device__ __forceinline__ float2 cfma(float2 a, float2 b, float2 c) {
    c.x = fmaf(a.x, b.x, fmaf(-a.y, b.y, c.x));
    c.y = fmaf(a.x, b.y, fmaf( a.y, b.x, c.y));
    return c;
}

// ---------------- scratch (device globals; no allocation allowed) ----------
__device__ float2 g_tmp  [B*CI*NY*NX];      // 33.5 MB  (fft intermediate, reused for ifft)
__device__ float2 g_alpha[B*CI*NY*NX];      // 33.5 MB
__device__ float2 g_A1   [CI*CO*M1*NY];
__device__ float2 g_A2   [CI*CO*M2*NX];
__device__ float2 g_E1   [CI*CO*M1*NY];
__device__ float2 g_E2   [CI*CO*M2*NX];
__device__ float2 g_H    [CI*CO*NY*NX];     // 134 MB
__device__ float2 g_res1 [B*CO*NY*NX];      // 33.5 MB
__device__ float2 g_T2   [B*CI*CO*M2*NY];   // 42 MB
__device__ float2 g_res2 [B*CO*M1*M2];
__device__ float2 g_G    [B*CI*CO*M2*NY];   // 42 MB

// ---------------- 128-point radix-2 DIT FFT (64 threads) -------------------
__device__ __forceinline__ void fft_stages(float2* s, int t, float dir) {
    #pragma unroll
    for (int len = 2; len <= 128; len <<= 1) {
        __syncthreads();
        int half = len >> 1;
        int p  = t & (half - 1);
        int i0 = ((t / half) * len) + p;
        int i1 = i0 + half;
        float sn, cs;
        sincospif(dir * 2.0f * (float)p / (float)len, &sn, &cs);
        float2 u = s[i0], v0 = s[i1];
        float2 v = make_float2(v0.x*cs - v0.y*sn, v0.x*sn + v0.y*cs);
        s[i0] = make_float2(u.x + v.x, u.y + v.y);
        s[i1] = make_float2(u.x - v.x, u.y - v.y);
    }
}

// forward FFT of real input rows: x -> g_tmp
__global__ void k_fft_rows_r(const float* __restrict__ x) {
    __shared__ float2 s[NX];
    int row = blockIdx.x;                 // (b*CI+i)*NY + y
    const float* xr = x + (size_t)row * NX;
    int t = threadIdx.x;
    s[t]      = make_float2(xr[__brev(t)      >> 25], 0.f);
    s[t + 64] = make_float2(xr[__brev(t + 64) >> 25], 0.f);
    fft_stages(s, t, -1.f);
    float2* o = g_tmp + (size_t)row * NX;
    o[t] = s[t]; o[t + 64] = s[t + 64];
}

// forward FFT of columns: g_tmp -> g_alpha
__global__ void k_fft_cols_fwd() {
    __shared__ float2 s[NY];
    int cb  = blockIdx.x;                 // img*NX + x
    int img = cb >> 7, xx = cb & 127;
    const float2* base = g_tmp + (size_t)img * NY * NX + xx;
    int t = threadIdx.x;
    s[t]      = base[(size_t)(__brev(t)      >> 25) * NX];
    s[t + 64] = base[(size_t)(__brev(t + 64) >> 25) * NX];
    fft_stages(s, t, -1.f);
    float2* ob = g_alpha + (size_t)img * NY * NX + xx;
    ob[(size_t)t * NX] = s[t]; ob[(size_t)(t + 64) * NX] = s[t + 64];
}

// inverse FFT rows: g_res1 -> g_tmp (no scaling here)
__global__ void k_ifft_rows() {
    __shared__ float2 s[NX];
    int row = blockIdx.x;
    const float2* xr = g_res1 + (size_t)row * NX;
    int t = threadIdx.x;
    s[t]      = xr[__brev(t)      >> 25];
    s[t + 64] = xr[__brev(t + 64) >> 25];
    fft_stages(s, t, +1.f);
    float2* o = g_tmp + (size_t)row * NX;
    o[t] = s[t]; o[t + 64] = s[t + 64];
}

// inverse FFT cols, write x1 = Re/(NY*NX) into out
__global__ void k_ifft_cols_real(float* __restrict__ out) {
    __shared__ float2 s[NY];
    int cb  = blockIdx.x;
    int img = cb >> 7, xx = cb & 127;
    const float2* base = g_tmp + (size_t)img * NY * NX + xx;
    int t = threadIdx.x;
    s[t]      = base[(size_t)(__brev(t)      >> 25) * NX];
    s[t + 64] = base[(size_t)(__brev(t + 64) >> 25) * NX];
    fft_stages(s, t, +1.f);
    const float INV = 1.0f / (float)(NY * NX);
    float* ob = out + (size_t)img * NY * NX + xx;
    ob[(size_t)t * NX]        = s[t].x * INV;
    ob[(size_t)(t + 64) * NX] = s[t + 64].x * INV;
}

// ---------------- pole factors A = 1/(i*lam - wp), E = exp(wp * t) ---------
__global__ void k_fac1(const float* __restrict__ wp_re, const float* __restrict__ wp_im,
                       const float* __restrict__ tv) {
    int ikp = blockIdx.x;                 // CI*CO*M1
    int o   = threadIdx.x;                // NY
    float wr = wp_re[ikp], wi = wp_im[ikp];
    float d = tv[1] - tv[0];
    float invnd = 1.0f / ((float)NY * d);
    float k = (o < NY/2) ? (float)o : (float)(o - NY);
    float lam = TWO_PI_F * k * invnd;
    float a = -wr, b = lam - wi;
    float inv = 1.0f / (a*a + b*b);
    g_A1[ikp*NY + o] = make_float2(a*inv, -b*inv);
    float t = tv[o];
    float e = expf(wr * t);
    float sn, cs; sincosf(wi * t, &sn, &cs);
    g_E1[ikp*NY + o] = make_float2(e*cs, e*sn);
}
__global__ void k_fac2(const float* __restrict__ wp_re, const float* __restrict__ wp_im,
                       const float* __restrict__ tv) {
    int ikq = blockIdx.x;                 // CI*CO*M2
    int x   = threadIdx.x;                // NX
    float wr = wp_re[ikq], wi = wp_im[ikq];
    float d = tv[1] - tv[0];
    float invnd = 1.0f / ((float)NX * d);
    float k = (x < NX/2) ? (float)x : (float)(x - NX);
    float lam = TWO_PI_F * k * invnd;
    float a = -wr, b = lam - wi;
    float inv = 1.0f / (a*a + b*b);
    g_A2[ikq*NX + x] = make_float2(a*inv, -b*inv);
    float t = tv[x];
    float e = expf(wr * t);
    float sn, cs; sincosf(wi * t, &sn, &cs);
    g_E2[ikq*NX + x] = make_float2(e*cs, e*sn);
}

// ---------------- Hsum[i,k,o,x] = sum_q (sum_p wr*A1[p,o]) * A2[q,x] -------
__global__ void k_hsum(const float* __restrict__ wr_re, const float* __restrict__ wr_im) {
    int ik = blockIdx.x;                  // CI*CO
    int t  = threadIdx.x;                 // 128
    __shared__ float2 wrS[M1*M2];
    __shared__ float2 A1S[M1][NY];
    __shared__ float2 U[M2][NY];
    if (t < M1*M2) wrS[t] = make_float2(wr_re[ik*M1*M2 + t], wr_im[ik*M1*M2 + t]);
    #pragma unroll
    for (int p = 0; p < M1; p++) A1S[p][t] = g_A1[(ik*M1 + p)*NY + t];
    float2 a2[M2];
    #pragma unroll
    for (int q = 0; q < M2; q++) a2[q] = g_A2[(ik*M2 + q)*NX + t];
    __syncthreads();
    #pragma unroll
    for (int q = 0; q < M2; q++) {
        float2 acc = make_float2(0.f, 0.f);
        #pragma unroll
        for (int p = 0; p < M1; p++) acc = cfma(wrS[p*M2 + q], A1S[p][t], acc);
        U[q][t] = acc;
    }
    __syncthreads();
    float2* H = g_H + (size_t)ik * NY * NX;
    for (int o = 0; o < NY; o++) {
        float2 acc = make_float2(0.f, 0.f);
        #pragma unroll
        for (int q = 0; q < M2; q++) acc = cfma(U[q][o], a2[q], acc);
        H[o*NX + t] = acc;
    }
}

// ---------------- res1[b,k,o,x] = sum_i alpha[b,i,o,x] * H[i,k,o,x] --------
// block = (k-tile of 4, o); thread = x; 8 batches accumulated in registers
__global__ void k_res1() {
    int o  = blockIdx.x & 127;
    int k0 = (blockIdx.x >> 7) * 4;
    int x  = threadIdx.x;
    float2 acc[4][B];
    #pragma unroll
    for (int kk = 0; kk < 4; kk++)
        #pragma unroll
        for (int b = 0; b < B; b++) acc[kk][b] = make_float2(0.f, 0.f);
    for (int i = 0; i < CI; i++) {
        float2 h[4];
        #pragma unroll
        for (int kk = 0; kk < 4; kk++)
            h[kk] = g_H[((size_t)(i*CO + k0 + kk) * NY + o) * NX + x];
        #pragma unroll
        for (int b = 0; b < B; b++) {
            float2 a = g_alpha[((size_t)(b*CI + i) * NY + o) * NX + x];
            #pragma unroll
            for (int kk = 0; kk < 4; kk++) acc[kk][b] = cfma(a, h[kk], acc[kk][b]);
        }
    }
    #pragma unroll
    for (int kk = 0; kk < 4; kk++)
        #pragma unroll
        for (int b = 0; b < B; b++)
            g_res1[((size_t)(b*CO + k0 + kk) * NY + o) * NX + x] = acc[kk][b];
}

// ---------------- T2[b,i,k,q,o] = sum_x alpha[b,i,o,x] * A2[i,k,q,x] -------
__global__ void k_T2() {
    __shared__ float2 alphaT[16][NX + 1];
    __shared__ float2 a2row[NX];
    int blk = blockIdx.x;                 // (b*CI+i)*8 + ot
    int ot  = blk & 7;
    int bi  = blk >> 3;
    int i   = bi & 31;
    int t   = threadIdx.x;
    const float2* abase = g_alpha + (size_t)bi * NY * NX + (size_t)(ot*16) * NX;
    #pragma unroll
    for (int r = 0; r < 16; r++) alphaT[r][t] = abase[r*NX + t];
    int oo = t >> 3, xi = t & 7;
    for (int kq = 0; kq < CO*M2; kq++) {
        __syncthreads();
        a2row[t] = g_A2[(size_t)(i*CO*M2 + kq) * NX + t];
        __syncthreads();
        float2 acc = make_float2(0.f, 0.f);
        #pragma unroll 4
        for (int xx = xi; xx < NX; xx += 8) acc = cfma(alphaT[oo][xx], a2row[xx], acc);
        #pragma unroll
        for (int off = 4; off; off >>= 1) {
            acc.x += __shfl_down_sync(0xffffffffu, acc.x, off);
            acc.y += __shfl_down_sync(0xffffffffu, acc.y, off);
        }
        if (xi == 0)
            g_T2[((size_t)bi * CO*M2 + kq) * NY + ot*16 + oo] = acc;
    }
}

// ---------------- res2[b,k,p,q] = sum_i wr * sum_o A1[p,o]*T2[q,o] ---------
__global__ void k_res2(const float* __restrict__ wr_re, const float* __restrict__ wr_im) {
    int bk = blockIdx.x;                  // b*CO + k
    int b = bk >> 5, k = bk & 31;
    int t = threadIdx.x;                  // o
    __shared__ float2 wrS[CI][M1*M2];
    for (int idx = t; idx < CI*M1*M2; idx += 128) {
        int i = idx / (M1*M2), pq = idx % (M1*M2);
        wrS[i][pq] = make_float2(wr_re[(i*CO + k)*M1*M2 + pq], wr_im[(i*CO + k)*M1*M2 + pq]);
    }
    __syncthreads();
    float2 acc[M1*M2];
    #pragma unroll
    for (int j = 0; j < M1*M2; j++) acc[j] = make_float2(0.f, 0.f);
    for (int i = 0; i < CI; i++) {
        float2 a1[M1], t2[M2];
        #pragma unroll
        for (int p = 0; p < M1; p++) a1[p] = g_A1[((i*CO + k)*M1 + p)*NY + t];
        #pragma unroll
        for (int q = 0; q < M2; q++) t2[q] = g_T2[(((size_t)(b*CI + i)*CO + k)*M2 + q)*NY + t];
        #pragma unroll
        for (int p = 0; p < M1; p++)
            #pragma unroll
            for (int q = 0; q < M2; q++) {
                float2 wa = cmul(wrS[i][p*M2 + q], a1[p]);
                acc[p*M2 + q] = cfma(wa, t2[q], acc[p*M2 + q]);
            }
    }
    #pragma unroll
    for (int j = 0; j < M1*M2; j++)
        #pragma unroll
        for (int off = 16; off; off >>= 1) {
            acc[j].x += __shfl_down_sync(0xffffffffu, acc[j].x, off);
            acc[j].y += __shfl_down_sync(0xffffffffu, acc[j].y, off);
        }
    __shared__ float2 red[4][M1*M2];
    int w = t >> 5, lane = t & 31;
    if (lane == 0) {
        #pragma unroll
        for (int j = 0; j < M1*M2; j++) red[w][j] = acc[j];
    }
    __syncthreads();
    if (t < M1*M2) {
        float2 s = red[0][t];
        #pragma unroll
        for (int w2 = 1; w2 < 4; w2++) { s.x += red[w2][t].x; s.y += red[w2][t].y; }
        g_res2[bk*M1*M2 + t] = s;
    }
}

// ---------------- G[b,c,k,q,z] = sum_p res2[b,c,p,q] * E1[c,k,p,z] ---------
__global__ void k_G() {
    int blk = blockIdx.x;                 // (b*CI+c)*CO + k
    int b = blk >> 10, c = (blk >> 5) & 31, k = blk & 31;
    int z = threadIdx.x;
    __shared__ float2 r2[M1*M2];
    if (z < M1*M2) r2[z] = g_res2[(b*CO + c)*M1*M2 + z];
    __syncthreads();
    float2 e1[M1];
    #pragma unroll
    for (int p = 0; p < M1; p++) e1[p] = g_E1[((c*CO + k)*M1 + p)*NY + z];
    #pragma unroll
    for (int q = 0; q < M2; q++) {
        float2 acc = make_float2(0.f, 0.f);
        #pragma unroll
        for (int p = 0; p < M1; p++) acc = cfma(r2[p*M2 + q], e1[p], acc);
        g_G[(((size_t)(b*CI + c)*CO + k)*M2 + q)*NY + z] = acc;
    }
}

// ---------------- out += Re(sum_{c,q} G * E2) / (NY*NX) --------------------
__global__ void k_x2add(float* __restrict__ out) {
    __shared__ float2 Gs[CI][M2][16];
    __shared__ float2 E2s[20][NX];
    int blk = blockIdx.x;                 // (b*CO+k)*8 + zt
    int zt  = blk & 7;
    int bk  = blk >> 3;
    int b = bk >> 5, k = bk & 31;
    int t = threadIdx.x;                  // x
    for (int idx = t; idx < CI*M2*16; idx += 128) {
        int c = idx / (M2*16), rem = idx % (M2*16), q = rem / 16, zz = rem % 16;
        Gs[c][q][zz] = g_G[(((size_t)(b*CI + c)*CO + k)*M2 + q)*NY + zt*16 + zz];
    }
    float acc[16];
    #pragma unroll
    for (int zz = 0; zz < 16; zz++) acc[zz] = 0.f;
    for (int c0 = 0; c0 < CI; c0 += 4) {
        __syncthreads();
        #pragma unroll
        for (int r = 0; r < 20; r++)
            E2s[r][t] = g_E2[((size_t)((c0 + r/M2)*CO + k)*M2 + (r % M2))*NX + t];
        __syncthreads();
        #pragma unroll
        for (int cc = 0; cc < 4; cc++)
            #pragma unroll
            for (int q = 0; q < M2; q++) {
                float2 e = E2s[cc*M2 + q][t];
                #pragma unroll
                for (int zz = 0; zz < 16; zz++) {
                    float2 g = Gs[c0 + cc][q][zz];
                    acc[zz] = fmaf(g.x, e.x, fmaf(-g.y, e.y, acc[zz]));
                }
            }
    }
    const float INV = 1.0f / (float)(NY * NX);
    float* ob = out + ((size_t)(b*CO + k)*NY + zt*16)*NX + t;
    #pragma unroll
    for (int zz = 0; zz < 16; zz++) ob[zz*NX] += acc[zz] * INV;
}

// ---------------------------------------------------------------------------
extern "C" void kernel_launch(void* const* d_in, const int* in_sizes, int n_in,
                              void* d_out, int out_size) {
    const float* x      = (const float*)d_in[0];
    const float* wp1_re = (const float*)d_in[1];
    const float* wp1_im = (const float*)d_in[2];
    const float* wp2_re = (const float*)d_in[3];
    const float* wp2_im = (const float*)d_in[4];
    const float* wr_re  = (const float*)d_in[5];
    const float* wr_im  = (const float*)d_in[6];
    const float* ty     = (const float*)d_in[7];
    const float* tx     = (const float*)d_in[8];
    float* out = (float*)d_out;

    k_fft_rows_r   <<<B*CI*NY, 64>>>(x);
    k_fft_cols_fwd <<<B*CI*NX, 64>>>();
    k_fac1         <<<CI*CO*M1, NY>>>(wp1_re, wp1_im, ty);
    k_fac2         <<<CI*CO*M2, NX>>>(wp2_re, wp2_im, tx);
    k_hsum         <<<CI*CO, 128>>>(wr_re, wr_im);
    k_res1         <<<(CO/4)*NY, 128>>>();
    k_T2           <<<B*CI*8, 128>>>();
    k_res2         <<<B*CO, 128>>>(wr_re, wr_im);
    k_G            <<<B*CI*CO, 128>>>();
    k_ifft_rows    <<<B*CO*NY, 64>>>();
    k_ifft_cols_real<<<B*CO*NX, 64>>>(out);
    k_x2add        <<<B*CO*8, 128>>>(out);
}

// round 2
// speedup vs baseline: 1.7487x; 1.7487x over previous
#include <cuda_runtime.h>

#define B   8
#define CI  32
#define CO  32
#define NY  128
#define NX  128
#define M1  4
#define M2  5

#define TWO_PI_F 6.283185307179586476925f

__device__ __forceinline__ float2 cmul(float2 a, float2 b) {
    return make_float2(a.x*b.x - a.y*b.y, a.x*b.y + a.y*b.x);
}
__device__ __forceinline__ float2 cfma(float2 a, float2 b, float2 c) {
    c.x = fmaf(a.x, b.x, fmaf(-a.y, b.y, c.x));
    c.y = fmaf(a.x, b.y, fmaf( a.y, b.x, c.y));
    return c;
}

// ---------------- scratch (device globals; no allocation allowed) ----------
__device__ float2 g_tw   [64];              // twiddle table W_128^j = e^{-i 2pi j/128}
__device__ float2 g_tmp  [B*CI*NY*NX];
__device__ float2 g_alpha[B*CI*NY*NX];
__device__ float2 g_A1   [CI*CO*M1*NY];
__device__ float2 g_A2   [CI*CO*M2*NX];
__device__ float2 g_E1   [CI*CO*M1*NY];
__device__ float2 g_E2   [CI*CO*M2*NX];
__device__ float2 g_H    [CI*CO*NY*NX];
__device__ float2 g_res1 [B*CO*NY*NX];
__device__ float2 g_T2   [B*CI*CO*M2*NY];
__device__ float2 g_res2 [B*CO*M1*M2];
__device__ float2 g_G    [B*CI*CO*M2*NY];

__global__ void k_tw() {
    int j = threadIdx.x;
    float sn, cs;
    sincospif(-(float)j / 64.f, &sn, &cs);
    g_tw[j] = make_float2(cs, sn);
}

// ---------------- 128-pt radix-2 DIT, table twiddles -----------------------
// 64 threads operate on one 128-elem shared row (input pre-bit-reversed).
template<int INV>
__device__ __forceinline__ void fft64th(float2* s, int tt, const float2* tws) {
    #pragma unroll
    for (int stage = 1; stage <= 7; stage++) {
        __syncthreads();
        int half = 1 << (stage - 1);
        int p  = tt & (half - 1);
        int i0 = ((tt >> (stage - 1)) << stage) + p;
        int i1 = i0 + half;
        float2 w = tws[p << (7 - stage)];
        float wy = INV ? -w.y : w.y;
        float2 u = s[i0], v0 = s[i1];
        float2 v = make_float2(v0.x*w.x - v0.y*wy, v0.x*wy + v0.y*w.x);
        s[i0] = make_float2(u.x + v.x, u.y + v.y);
        s[i1] = make_float2(u.x - v.x, u.y - v.y);
    }
}

// forward FFT of real rows: x -> g_tmp  (2 rows per block)
__global__ void k_fft_rows_f(const float* __restrict__ x) {
    __shared__ float2 s[2][NX];
    __shared__ float2 tws[64];
    int t = threadIdx.x, r = t >> 6, tt = t & 63;
    if (t < 64) tws[t] = g_tw[t];
    size_t row = (size_t)blockIdx.x * 2 + r;
    const float* xr = x + row * NX;
    s[r][tt]      = make_float2(xr[__brev(tt)      >> 25], 0.f);
    s[r][tt + 64] = make_float2(xr[__brev(tt + 64) >> 25], 0.f);
    fft64th<0>(s[r], tt, tws);
    float2* o = g_tmp + row * NX;
    o[tt] = s[r][tt]; o[tt + 64] = s[r][tt + 64];
}

// inverse FFT rows: g_res1 -> g_tmp  (2 rows per block)
__global__ void k_ifft_rows_f() {
    __shared__ float2 s[2][NX];
    __shared__ float2 tws[64];
    int t = threadIdx.x, r = t >> 6, tt = t & 63;
    if (t < 64) tws[t] = g_tw[t];
    size_t row = (size_t)blockIdx.x * 2 + r;
    const float2* xr = g_res1 + row * NX;
    s[r][tt]      = xr[__brev(tt)      >> 25];
    s[r][tt + 64] = xr[__brev(tt + 64) >> 25];
    fft64th<1>(s[r], tt, tws);
    float2* o = g_tmp + row * NX;
    o[tt] = s[r][tt]; o[tt + 64] = s[r][tt + 64];
}

// ---------------- tiled column FFT: 16 columns per block -------------------
template<int INV>
__device__ __forceinline__ void fft_col(float2 (*tile)[17], int tg, int tx, const float2* tws) {
    #pragma unroll
    for (int stage = 1; stage <= 7; stage++) {
        __syncthreads();
        int half = 1 << (stage - 1);
        #pragma unroll
        for (int m = 0; m < 8; m++) {
            int j  = tg + 8 * m;
            int p  = j & (half - 1);
            int i0 = ((j >> (stage - 1)) << stage) + p;
            int i1 = i0 + half;
            float2 w = tws[p << (7 - stage)];
            float wy = INV ? -w.y : w.y;
            float2 u = tile[i0][tx], v0 = tile[i1][tx];
            float2 v = make_float2(v0.x*w.x - v0.y*wy, v0.x*wy + v0.y*w.x);
            tile[i0][tx] = make_float2(u.x + v.x, u.y + v.y);
            tile[i1][tx] = make_float2(u.x - v.x, u.y - v.y);
        }
    }
}

// forward columns: g_tmp -> g_alpha
__global__ void k_fft_cols_f() {
    __shared__ float2 tile[NY][17];
    __shared__ float2 tws[64];
    int t = threadIdx.x;
    if (t < 64) tws[t] = g_tw[t];
    int blk = blockIdx.x;                 // img*8 + xt
    int xt = blk & 7, img = blk >> 3;
    int x0 = xt * 16;
    int tg = t >> 4, tx = t & 15;
    const float2* base = g_tmp + (size_t)img * NY * NX + x0;
    #pragma unroll
    for (int c = 0; c < 16; c++) {
        int y = c * 8 + tg;
        tile[__brev(y) >> 25][tx] = base[(size_t)y * NX + tx];
    }
    fft_col<0>(tile, tg, tx, tws);
    __syncthreads();
    float2* ob = g_alpha + (size_t)img * NY * NX + x0;
    #pragma unroll
    for (int c = 0; c < 16; c++) {
        int y = c * 8 + tg;
        ob[(size_t)y * NX + tx] = tile[y][tx];
    }
}

// inverse columns + real part + scale: g_tmp -> out
__global__ void k_ifft_cols_r(float* __restrict__ out) {
    __shared__ float2 tile[NY][17];
    __shared__ float2 tws[64];
    int t = threadIdx.x;
    if (t < 64) tws[t] = g_tw[t];
    int blk = blockIdx.x;
    int xt = blk & 7, img = blk >> 3;
    int x0 = xt * 16;
    int tg = t >> 4, tx = t & 15;
    const float2* base = g_tmp + (size_t)img * NY * NX + x0;
    #pragma unroll
    for (int c = 0; c < 16; c++) {
        int y = c * 8 + tg;
        tile[__brev(y) >> 25][tx] = base[(size_t)y * NX + tx];
    }
    fft_col<1>(tile, tg, tx, tws);
    __syncthreads();
    const float INV = 1.0f / (float)(NY * NX);
    float* ob = out + (size_t)img * NY * NX + x0;
    #pragma unroll
    for (int c = 0; c < 16; c++) {
        int y = c * 8 + tg;
        ob[(size_t)y * NX + tx] = tile[y][tx].x * INV;
    }
}

// ---------------- pole factors A = 1/(i*lam - wp), E = exp(wp * t) ---------
__global__ void k_fac1(const float* __restrict__ wp_re, const float* __restrict__ wp_im,
                       const float* __restrict__ tv) {
    int ikp = blockIdx.x;
    int o   = threadIdx.x;
    float wr = wp_re[ikp], wi = wp_im[ikp];
    float d = tv[1] - tv[0];
    float invnd = 1.0f / ((float)NY * d);
    float k = (o < NY/2) ? (float)o : (float)(o - NY);
    float lam = TWO_PI_F * k * invnd;
    float a = -wr, b = lam - wi;
    float inv = 1.0f / (a*a + b*b);
    g_A1[ikp*NY + o] = make_float2(a*inv, -b*inv);
    float t = tv[o];
    float e = expf(wr * t);
    float sn, cs; sincosf(wi * t, &sn, &cs);
    g_E1[ikp*NY + o] = make_float2(e*cs, e*sn);
}
__global__ void k_fac2(const float* __restrict__ wp_re, const float* __restrict__ wp_im,
                       const float* __restrict__ tv) {
    int ikq = blockIdx.x;
    int x   = threadIdx.x;
    float wr = wp_re[ikq], wi = wp_im[ikq];
    float d = tv[1] - tv[0];
    float invnd = 1.0f / ((float)NX * d);
    float k = (x < NX/2) ? (float)x : (float)(x - NX);
    float lam = TWO_PI_F * k * invnd;
    float a = -wr, b = lam - wi;
    float inv = 1.0f / (a*a + b*b);
    g_A2[ikq*NX + x] = make_float2(a*inv, -b*inv);
    float t = tv[x];
    float e = expf(wr * t);
    float sn, cs; sincosf(wi * t, &sn, &cs);
    g_E2[ikq*NX + x] = make_float2(e*cs, e*sn);
}

// ---------------- Hsum[i,k,o,x] = sum_q (sum_p wr*A1[p,o]) * A2[q,x] -------
__global__ void k_hsum(const float* __restrict__ wr_re, const float* __restrict__ wr_im) {
    int ik = blockIdx.x;
    int t  = threadIdx.x;
    __shared__ float2 wrS[M1*M2];
    __shared__ float2 A1S[M1][NY];
    __shared__ float2 U[M2][NY];
    if (t < M1*M2) wrS[t] = make_float2(wr_re[ik*M1*M2 + t], wr_im[ik*M1*M2 + t]);
    #pragma unroll
    for (int p = 0; p < M1; p++) A1S[p][t] = g_A1[(ik*M1 + p)*NY + t];
    float2 a2[M2];
    #pragma unroll
    for (int q = 0; q < M2; q++) a2[q] = g_A2[(ik*M2 + q)*NX + t];
    __syncthreads();
    #pragma unroll
    for (int q = 0; q < M2; q++) {
        float2 acc = make_float2(0.f, 0.f);
        #pragma unroll
        for (int p = 0; p < M1; p++) acc = cfma(wrS[p*M2 + q], A1S[p][t], acc);
        U[q][t] = acc;
    }
    __syncthreads();
    float2* H = g_H + (size_t)ik * NY * NX;
    for (int o = 0; o < NY; o++) {
        float2 acc = make_float2(0.f, 0.f);
        #pragma unroll
        for (int q = 0; q < M2; q++) acc = cfma(U[q][o], a2[q], acc);
        H[o*NX + t] = acc;
    }
}

// ---------------- res1[b,k,o,x] = sum_i alpha[b,i,o,x] * H[i,k,o,x] --------
__global__ void k_res1() {
    int o  = blockIdx.x & 127;
    int k0 = (blockIdx.x >> 7) * 4;
    int x  = threadIdx.x;
    float2 acc[4][B];
    #pragma unroll
    for (int kk = 0; kk < 4; kk++)
        #pragma unroll
        for (int b = 0; b < B; b++) acc[kk][b] = make_float2(0.f, 0.f);
    for (int i = 0; i < CI; i++) {
        float2 h[4];
        #pragma unroll
        for (int kk = 0; kk < 4; kk++)
            h[kk] = g_H[((size_t)(i*CO + k0 + kk) * NY + o) * NX + x];
        #pragma unroll
        for (int b = 0; b < B; b++) {
            float2 a = g_alpha[((size_t)(b*CI + i) * NY + o) * NX + x];
            #pragma unroll
            for (int kk = 0; kk < 4; kk++) acc[kk][b] = cfma(a, h[kk], acc[kk][b]);
        }
    }
    #pragma unroll
    for (int kk = 0; kk < 4; kk++)
        #pragma unroll
        for (int b = 0; b < B; b++)
            g_res1[((size_t)(b*CO + k0 + kk) * NY + o) * NX + x] = acc[kk][b];
}

// ---------------- T2[b,i,k,q,o] = sum_x alpha[b,i,o,x] * A2[i,k,q,x] -------
// alpha tile in registers (reused x160), A2 staged 8 rows per sync.
__global__ void k_T2() {
    __shared__ float2 a2s[8][NX];
    int blk = blockIdx.x;                 // (b*CI+i)*8 + ot
    int ot  = blk & 7;
    int bi  = blk >> 3;
    int i   = bi & 31;
    int t   = threadIdx.x;
    int oo = t >> 3, xi = t & 7;
    float2 areg[16];
    const float2* abase = g_alpha + (size_t)bi * NY * NX + (size_t)(ot*16 + oo) * NX;
    #pragma unroll
    for (int m = 0; m < 16; m++) areg[m] = abase[xi + 8*m];
    for (int kc = 0; kc < CO*M2; kc += 8) {
        __syncthreads();
        #pragma unroll
        for (int r = 0; r < 8; r++)
            a2s[r][t] = g_A2[(size_t)(i*CO*M2 + kc + r) * NX + t];
        __syncthreads();
        #pragma unroll
        for (int r = 0; r < 8; r++) {
            float2 acc = make_float2(0.f, 0.f);
            #pragma unroll
            for (int m = 0; m < 16; m++) acc = cfma(areg[m], a2s[r][xi + 8*m], acc);
            #pragma unroll
            for (int off = 4; off; off >>= 1) {
                acc.x += __shfl_down_sync(0xffffffffu, acc.x, off);
                acc.y += __shfl_down_sync(0xffffffffu, acc.y, off);
            }
            if (xi == 0)
                g_T2[((size_t)bi * CO*M2 + kc + r) * NY + ot*16 + oo] = acc;
        }
    }
}

// ---------------- res2[b,k,p,q] = sum_i wr * sum_o A1[p,o]*T2[q,o] ---------
__global__ void k_res2(const float* __restrict__ wr_re, const float* __restrict__ wr_im) {
    int bk = blockIdx.x;
    int b = bk >> 5, k = bk & 31;
    int t = threadIdx.x;
    __shared__ float2 wrS[CI][M1*M2];
    for (int idx = t; idx < CI*M1*M2; idx += 128) {
        int i = idx / (M1*M2), pq = idx % (M1*M2);
        wrS[i][pq] = make_float2(wr_re[(i*CO + k)*M1*M2 + pq], wr_im[(i*CO + k)*M1*M2 + pq]);
    }
    __syncthreads();
    float2 acc[M1*M2];
    #pragma unroll
    for (int j = 0; j < M1*M2; j++) acc[j] = make_float2(0.f, 0.f);
    for (int i = 0; i < CI; i++) {
        float2 a1[M1], t2[M2];
        #pragma unroll
        for (int p = 0; p < M1; p++) a1[p] = g_A1[((i*CO + k)*M1 + p)*NY + t];
        #pragma unroll
        for (int q = 0; q < M2; q++) t2[q] = g_T2[(((size_t)(b*CI + i)*CO + k)*M2 + q)*NY + t];
        #pragma unroll
        for (int p = 0; p < M1; p++)
            #pragma unroll
            for (int q = 0; q < M2; q++) {
                float2 wa = cmul(wrS[i][p*M2 + q], a1[p]);
                acc[p*M2 + q] = cfma(wa, t2[q], acc[p*M2 + q]);
            }
    }
    #pragma unroll
    for (int j = 0; j < M1*M2; j++)
        #pragma unroll
        for (int off = 16; off; off >>= 1) {
            acc[j].x += __shfl_down_sync(0xffffffffu, acc[j].x, off);
            acc[j].y += __shfl_down_sync(0xffffffffu, acc[j].y, off);
        }
    __shared__ float2 red[4][M1*M2];
    int w = t >> 5, lane = t & 31;
    if (lane == 0) {
        #pragma unroll
        for (int j = 0; j < M1*M2; j++) red[w][j] = acc[j];
    }
    __syncthreads();
    if (t < M1*M2) {
        float2 s = red[0][t];
        #pragma unroll
        for (int w2 = 1; w2 < 4; w2++) { s.x += red[w2][t].x; s.y += red[w2][t].y; }
        g_res2[bk*M1*M2 + t] = s;
    }
}

// ---------------- G[b,c,k,q,z] = sum_p res2[b,c,p,q] * E1[c,k,p,z] ---------
__global__ void k_G() {
    int blk = blockIdx.x;
    int b = blk >> 10, c = (blk >> 5) & 31, k = blk & 31;
    int z = threadIdx.x;
    __shared__ float2 r2[M1*M2];
    if (z < M1*M2) r2[z] = g_res2[(b*CO + c)*M1*M2 + z];
    __syncthreads();
    float2 e1[M1];
    #pragma unroll
    for (int p = 0; p < M1; p++) e1[p] = g_E1[((c*CO + k)*M1 + p)*NY + z];
    #pragma unroll
    for (int q = 0; q < M2; q++) {
        float2 acc = make_float2(0.f, 0.f);
        #pragma unroll
        for (int p = 0; p < M1; p++) acc = cfma(r2[p*M2 + q], e1[p], acc);
        g_G[(((size_t)(b*CI + c)*CO + k)*M2 + q)*NY + z] = acc;
    }
}

// ---------------- x2: out += Re( G[z, cq] * E2[cq, x] ) / (NY*NX) ----------
// Register-tiled real GEMM per (b,k): 128(z) x 128(x), K=160 complex.
__global__ void k_x2(float* __restrict__ out) {
    __shared__ float2 Gs[16][NY];         // [k-chunk][z]
    __shared__ float2 Es[16][NX];         // [k-chunk][x]
    int bk = blockIdx.x;
    int b = bk >> 5, k = bk & 31;
    int t = threadIdx.x;                  // 256
    int tz = t >> 4, tx = t & 15;         // 16 x 16 thread grid
    float acc[8][8];
    #pragma unroll
    for (int a = 0; a < 8; a++)
        #pragma unroll
        for (int bb = 0; bb < 8; bb++) acc[a][bb] = 0.f;
    for (int k0 = 0; k0 < CI*M2; k0 += 16) {
        __syncthreads();
        for (int l = t; l < 16*128; l += 256) {
            int r = l >> 7, z = l & 127;
            int cq = k0 + r; int c = cq / M2, q = cq % M2;
            Gs[r][z] = g_G[(((size_t)(b*CI + c)*CO + k)*M2 + q)*NY + z];
            Es[r][z] = g_E2[((size_t)(c*CO + k)*M2 + q)*NX + z];
        }
        __syncthreads();
        #pragma unroll
        for (int kk = 0; kk < 16; kk++) {
            float2 gr[8], er[8];
            #pragma unroll
            for (int a = 0; a < 8; a++) gr[a] = Gs[kk][tz + 16*a];
            #pragma unroll
            for (int bb = 0; bb < 8; bb++) er[bb] = Es[kk][tx + 16*bb];
            #pragma unroll
            for (int a = 0; a < 8; a++)
                #pragma unroll
                for (int bb = 0; bb < 8; bb++)
                    acc[a][bb] = fmaf(gr[a].x, er[bb].x,
                                 fmaf(-gr[a].y, er[bb].y, acc[a][bb]));
        }
    }
    const float INV = 1.0f / (float)(NY * NX);
    float* ob = out + (size_t)(b*CO + k) * NY * NX;
    #pragma unroll
    for (int a = 0; a < 8; a++)
        #pragma unroll
        for (int bb = 0; bb < 8; bb++)
            ob[(size_t)(tz + 16*a) * NX + tx + 16*bb] += acc[a][bb] * INV;
}

// ---------------------------------------------------------------------------
extern "C" void kernel_launch(void* const* d_in, const int* in_sizes, int n_in,
                              void* d_out, int out_size) {
    const float* x      = (const float*)d_in[0];
    const float* wp1_re = (const float*)d_in[1];
    const float* wp1_im = (const float*)d_in[2];
    const float* wp2_re = (const float*)d_in[3];
    const float* wp2_im = (const float*)d_in[4];
    const float* wr_re  = (const float*)d_in[5];
    const float* wr_im  = (const float*)d_in[6];
    const float* ty     = (const float*)d_in[7];
    const float* tx     = (const float*)d_in[8];
    float* out = (float*)d_out;

    k_tw          <<<1, 64>>>();
    k_fft_rows_f  <<<B*CI*NY/2, 128>>>(x);
    k_fft_cols_f  <<<B*CI*8, 128>>>();
    k_fac1        <<<CI*CO*M1, NY>>>(wp1_re, wp1_im, ty);
    k_fac2        <<<CI*CO*M2, NX>>>(wp2_re, wp2_im, tx);
    k_hsum        <<<CI*CO, 128>>>(wr_re, wr_im);
    k_res1        <<<(CO/4)*NY, 128>>>();
    k_T2          <<<B*CI*8, 128>>>();
    k_res2        <<<B*CO, 128>>>(wr_re, wr_im);
    k_G           <<<B*CI*CO, 128>>>();
    k_ifft_rows_f <<<B*CO*NY/2, 128>>>();
    k_ifft_cols_r <<<B*CO*8, 128>>>(out);
    k_x2          <<<B*CO, 256>>>(out);
}

// round 3
// speedup vs baseline: 1.9557x; 1.1184x over previous
#include <cuda_runtime.h>

#define B   8
#define CI  32
#define CO  32
#define NY  128
#define NX  128
#define M1  4
#define M2  5

#define TWO_PI_F 6.283185307179586476925f

__device__ __forceinline__ float2 cmul(float2 a, float2 b) {
    return make_float2(a.x*b.x - a.y*b.y, a.x*b.y + a.y*b.x);
}
__device__ __forceinline__ float2 cfma(float2 a, float2 b, float2 c) {
    c.x = fmaf(a.x, b.x, fmaf(-a.y, b.y, c.x));
    c.y = fmaf(a.x, b.y, fmaf( a.y, b.x, c.y));
    return c;
}

// ---------------- scratch (device globals; no allocation allowed) ----------
__device__ float2 g_tw   [64];
__device__ float2 g_tmp  [B*CI*NY*NX];
__device__ float2 g_alpha[B*CI*NY*NX];
__device__ float2 g_A1   [CI*CO*M1*NY];
__device__ float2 g_A2   [CI*CO*M2*NX];
__device__ float2 g_E1   [CI*CO*M1*NY];
__device__ float2 g_E2   [CI*CO*M2*NX];
__device__ float2 g_H    [CI*CO*NY*NX];
__device__ float2 g_res1 [B*CO*NY*NX];
__device__ float2 g_T2   [B*CI*CO*M2*NY];
__device__ float2 g_res2 [B*CO*M1*M2];
__device__ float2 g_G    [B*CI*CO*M2*NY];

__global__ void k_tw() {
    int j = threadIdx.x;
    float sn, cs;
    sincospif(-(float)j / 64.f, &sn, &cs);
    g_tw[j] = make_float2(cs, sn);
}

// ---------------- 128-pt radix-2 DIT, table twiddles -----------------------
template<int INV>
__device__ __forceinline__ void fft64th(float2* s, int tt, const float2* tws) {
    #pragma unroll
    for (int stage = 1; stage <= 7; stage++) {
        __syncthreads();
        int half = 1 << (stage - 1);
        int p  = tt & (half - 1);
        int i0 = ((tt >> (stage - 1)) << stage) + p;
        int i1 = i0 + half;
        float2 w = tws[p << (7 - stage)];
        float wy = INV ? -w.y : w.y;
        float2 u = s[i0], v0 = s[i1];
        float2 v = make_float2(v0.x*w.x - v0.y*wy, v0.x*wy + v0.y*w.x);
        s[i0] = make_float2(u.x + v.x, u.y + v.y);
        s[i1] = make_float2(u.x - v.x, u.y - v.y);
    }
}

__global__ void k_fft_rows_f(const float* __restrict__ x) {
    __shared__ float2 s[2][NX];
    __shared__ float2 tws[64];
    int t = threadIdx.x, r = t >> 6, tt = t & 63;
    if (t < 64) tws[t] = g_tw[t];
    size_t row = (size_t)blockIdx.x * 2 + r;
    const float* xr = x + row * NX;
    s[r][tt]      = make_float2(xr[__brev(tt)      >> 25], 0.f);
    s[r][tt + 64] = make_float2(xr[__brev(tt + 64) >> 25], 0.f);
    fft64th<0>(s[r], tt, tws);
    float2* o = g_tmp + row * NX;
    o[tt] = s[r][tt]; o[tt + 64] = s[r][tt + 64];
}

__global__ void k_ifft_rows_f() {
    __shared__ float2 s[2][NX];
    __shared__ float2 tws[64];
    int t = threadIdx.x, r = t >> 6, tt = t & 63;
    if (t < 64) tws[t] = g_tw[t];
    size_t row = (size_t)blockIdx.x * 2 + r;
    const float2* xr = g_res1 + row * NX;
    s[r][tt]      = xr[__brev(tt)      >> 25];
    s[r][tt + 64] = xr[__brev(tt + 64) >> 25];
    fft64th<1>(s[r], tt, tws);
    float2* o = g_tmp + row * NX;
    o[tt] = s[r][tt]; o[tt + 64] = s[r][tt + 64];
}

template<int INV>
__device__ __forceinline__ void fft_col(float2 (*tile)[17], int tg, int tx, const float2* tws) {
    #pragma unroll
    for (int stage = 1; stage <= 7; stage++) {
        __syncthreads();
        int half = 1 << (stage - 1);
        #pragma unroll
        for (int m = 0; m < 8; m++) {
            int j  = tg + 8 * m;
            int p  = j & (half - 1);
            int i0 = ((j >> (stage - 1)) << stage) + p;
            int i1 = i0 + half;
            float2 w = tws[p << (7 - stage)];
            float wy = INV ? -w.y : w.y;
            float2 u = tile[i0][tx], v0 = tile[i1][tx];
            float2 v = make_float2(v0.x*w.x - v0.y*wy, v0.x*wy + v0.y*w.x);
            tile[i0][tx] = make_float2(u.x + v.x, u.y + v.y);
            tile[i1][tx] = make_float2(u.x - v.x, u.y - v.y);
        }
    }
}

__global__ void k_fft_cols_f() {
    __shared__ float2 tile[NY][17];
    __shared__ float2 tws[64];
    int t = threadIdx.x;
    if (t < 64) tws[t] = g_tw[t];
    int blk = blockIdx.x;
    int xt = blk & 7, img = blk >> 3;
    int x0 = xt * 16;
    int tg = t >> 4, tx = t & 15;
    const float2* base = g_tmp + (size_t)img * NY * NX + x0;
    #pragma unroll
    for (int c = 0; c < 16; c++) {
        int y = c * 8 + tg;
        tile[__brev(y) >> 25][tx] = base[(size_t)y * NX + tx];
    }
    fft_col<0>(tile, tg, tx, tws);
    __syncthreads();
    float2* ob = g_alpha + (size_t)img * NY * NX + x0;
    #pragma unroll
    for (int c = 0; c < 16; c++) {
        int y = c * 8 + tg;
        ob[(size_t)y * NX + tx] = tile[y][tx];
    }
}

__global__ void k_ifft_cols_r(float* __restrict__ out) {
    __shared__ float2 tile[NY][17];
    __shared__ float2 tws[64];
    int t = threadIdx.x;
    if (t < 64) tws[t] = g_tw[t];
    int blk = blockIdx.x;
    int xt = blk & 7, img = blk >> 3;
    int x0 = xt * 16;
    int tg = t >> 4, tx = t & 15;
    const float2* base = g_tmp + (size_t)img * NY * NX + x0;
    #pragma unroll
    for (int c = 0; c < 16; c++) {
        int y = c * 8 + tg;
        tile[__brev(y) >> 25][tx] = base[(size_t)y * NX + tx];
    }
    fft_col<1>(tile, tg, tx, tws);
    __syncthreads();
    const float INV = 1.0f / (float)(NY * NX);
    float* ob = out + (size_t)img * NY * NX + x0;
    #pragma unroll
    for (int c = 0; c < 16; c++) {
        int y = c * 8 + tg;
        ob[(size_t)y * NX + tx] = tile[y][tx].x * INV;
    }
}

// ---------------- merged pole factors --------------------------------------
__global__ void k_fac(const float* __restrict__ wp1_re, const float* __restrict__ wp1_im,
                      const float* __restrict__ wp2_re, const float* __restrict__ wp2_im,
                      const float* __restrict__ ty, const float* __restrict__ tx) {
    int blk = blockIdx.x;
    int o   = threadIdx.x;
    if (blk < CI*CO*M1) {
        int ikp = blk;
        float wr = wp1_re[ikp], wi = wp1_im[ikp];
        float d = ty[1] - ty[0];
        float invnd = 1.0f / ((float)NY * d);
        float k = (o < NY/2) ? (float)o : (float)(o - NY);
        float lam = TWO_PI_F * k * invnd;
        float a = -wr, b = lam - wi;
        float inv = 1.0f / (a*a + b*b);
        g_A1[ikp*NY + o] = make_float2(a*inv, -b*inv);
        float t = ty[o];
        float e = expf(wr * t);
        float sn, cs; sincosf(wi * t, &sn, &cs);
        g_E1[ikp*NY + o] = make_float2(e*cs, e*sn);
    } else {
        int ikq = blk - CI*CO*M1;
        float wr = wp2_re[ikq], wi = wp2_im[ikq];
        float d = tx[1] - tx[0];
        float invnd = 1.0f / ((float)NX * d);
        float k = (o < NX/2) ? (float)o : (float)(o - NX);
        float lam = TWO_PI_F * k * invnd;
        float a = -wr, b = lam - wi;
        float inv = 1.0f / (a*a + b*b);
        g_A2[ikq*NX + o] = make_float2(a*inv, -b*inv);
        float t = tx[o];
        float e = expf(wr * t);
        float sn, cs; sincosf(wi * t, &sn, &cs);
        g_E2[ikq*NX + o] = make_float2(e*cs, e*sn);
    }
}

// ---------------- Hsum[i,k,o,x] (streaming stores) -------------------------
__global__ void k_hsum(const float* __restrict__ wr_re, const float* __restrict__ wr_im) {
    int ik = blockIdx.x;
    int t  = threadIdx.x;
    __shared__ float2 wrS[M1*M2];
    __shared__ float2 A1S[M1][NY];
    __shared__ float2 U[M2][NY];
    if (t < M1*M2) wrS[t] = make_float2(wr_re[ik*M1*M2 + t], wr_im[ik*M1*M2 + t]);
    #pragma unroll
    for (int p = 0; p < M1; p++) A1S[p][t] = g_A1[(ik*M1 + p)*NY + t];
    float2 a2[M2];
    #pragma unroll
    for (int q = 0; q < M2; q++) a2[q] = g_A2[(ik*M2 + q)*NX + t];
    __syncthreads();
    #pragma unroll
    for (int q = 0; q < M2; q++) {
        float2 acc = make_float2(0.f, 0.f);
        #pragma unroll
        for (int p = 0; p < M1; p++) acc = cfma(wrS[p*M2 + q], A1S[p][t], acc);
        U[q][t] = acc;
    }
    __syncthreads();
    float2* H = g_H + (size_t)ik * NY * NX;
    for (int o = 0; o < NY; o++) {
        float2 acc = make_float2(0.f, 0.f);
        #pragma unroll
        for (int q = 0; q < M2; q++) acc = cfma(U[q][o], a2[q], acc);
        __stcs(&H[o*NX + t], acc);
    }
}

// ---------------- res1: H read streaming, alpha L2-resident ----------------
__global__ void k_res1() {
    int o  = blockIdx.x & 127;
    int k0 = (blockIdx.x >> 7) * 4;
    int x  = threadIdx.x;
    float2 acc[4][B];
    #pragma unroll
    for (int kk = 0; kk < 4; kk++)
        #pragma unroll
        for (int b = 0; b < B; b++) acc[kk][b] = make_float2(0.f, 0.f);
    for (int i = 0; i < CI; i++) {
        float2 h[4];
        #pragma unroll
        for (int kk = 0; kk < 4; kk++)
            h[kk] = __ldcs(&g_H[((size_t)(i*CO + k0 + kk) * NY + o) * NX + x]);
        #pragma unroll
        for (int b = 0; b < B; b++) {
            float2 a = g_alpha[((size_t)(b*CI + i) * NY + o) * NX + x];
            #pragma unroll
            for (int kk = 0; kk < 4; kk++) acc[kk][b] = cfma(a, h[kk], acc[kk][b]);
        }
    }
    #pragma unroll
    for (int kk = 0; kk < 4; kk++)
        #pragma unroll
        for (int b = 0; b < B; b++)
            g_res1[((size_t)(b*CO + k0 + kk) * NY + o) * NX + x] = acc[kk][b];
}

// ---------------- T2 as smem GEMM: C[kq,o] = sum_x A2[kq,x]*alpha[o,x] -----
// One block per (b,i) image. alpha image + A2 chunk in dynamic smem.
// 128 threads, 8x8 complex register tiles, zero shuffles.
#define T2_CHUNK 64
#define T2_SMEM ((128*129 + T2_CHUNK*129) * sizeof(float2))
extern __shared__ float2 t2sm[];
__global__ void __launch_bounds__(128, 1) k_T2() {
    float2* alphaS = t2sm;                   // [128][129]
    float2* a2S    = t2sm + 128*129;         // [T2_CHUNK][129]
    int bi = blockIdx.x;                     // b*CI + i
    int i  = bi & 31;
    int t  = threadIdx.x;
    // load alpha image (coalesced: thread t = column x)
    const float2* A = g_alpha + (size_t)bi * NY * NX;
    #pragma unroll 4
    for (int r = 0; r < 128; r++)
        alphaS[r*129 + t] = A[(size_t)r * NX + t];
    int u = t >> 4;                          // kq-group 0..7
    int v = t & 15;                          // o-group  0..15
    for (int kq0 = 0; kq0 < CO*M2; kq0 += T2_CHUNK) {
        int rows = CO*M2 - kq0; if (rows > T2_CHUNK) rows = T2_CHUNK;
        __syncthreads();
        for (int l = t; l < rows*128; l += 128) {
            int rr = l >> 7, xx = l & 127;
            a2S[rr*129 + xx] = g_A2[(size_t)(i*CO*M2 + kq0 + rr) * NX + xx];
        }
        __syncthreads();
        float2 acc[8][8];
        #pragma unroll
        for (int j = 0; j < 8; j++)
            #pragma unroll
            for (int jj = 0; jj < 8; jj++) acc[j][jj] = make_float2(0.f, 0.f);
        for (int x = 0; x < 128; x++) {
            float2 br[8], ar[8];
            #pragma unroll
            for (int j = 0; j < 8; j++)  br[j]  = a2S[(u*8 + j)*129 + x];
            #pragma unroll
            for (int jj = 0; jj < 8; jj++) ar[jj] = alphaS[(v + 16*jj)*129 + x];
            #pragma unroll
            for (int j = 0; j < 8; j++)
                #pragma unroll
                for (int jj = 0; jj < 8; jj++)
                    acc[j][jj] = cfma(ar[jj], br[j], acc[j][jj]);
        }
        #pragma unroll
        for (int j = 0; j < 8; j++) {
            int kq = u*8 + j;
            if (kq < rows) {
                float2* dst = g_T2 + ((size_t)bi * CO*M2 + kq0 + kq) * NY;
                #pragma unroll
                for (int jj = 0; jj < 8; jj++)
                    dst[v + 16*jj] = acc[j][jj];
            }
        }
    }
}

// ---------------- res2[b,k,p,q] = sum_i wr * sum_o A1[p,o]*T2[q,o] ---------
__global__ void k_res2(const float* __restrict__ wr_re, const float* __restrict__ wr_im) {
    int bk = blockIdx.x;
    int b = bk >> 5, k = bk & 31;
    int t = threadIdx.x;
    __shared__ float2 wrS[CI][M1*M2];
    for (int idx = t; idx < CI*M1*M2; idx += 128) {
        int i = idx / (M1*M2), pq = idx % (M1*M2);
        wrS[i][pq] = make_float2(wr_re[(i*CO + k)*M1*M2 + pq], wr_im[(i*CO + k)*M1*M2 + pq]);
    }
    __syncthreads();
    float2 acc[M1*M2];
    #pragma unroll
    for (int j = 0; j < M1*M2; j++) acc[j] = make_float2(0.f, 0.f);
    for (int i = 0; i < CI; i++) {
        float2 a1[M1], t2[M2];
        #pragma unroll
        for (int p = 0; p < M1; p++) a1[p] = g_A1[((i*CO + k)*M1 + p)*NY + t];
        #pragma unroll
        for (int q = 0; q < M2; q++) t2[q] = g_T2[(((size_t)(b*CI + i)*CO + k)*M2 + q)*NY + t];
        #pragma unroll
        for (int p = 0; p < M1; p++)
            #pragma unroll
            for (int q = 0; q < M2; q++) {
                float2 wa = cmul(wrS[i][p*M2 + q], a1[p]);
                acc[p*M2 + q] = cfma(wa, t2[q], acc[p*M2 + q]);
            }
    }
    #pragma unroll
    for (int j = 0; j < M1*M2; j++)
        #pragma unroll
        for (int off = 16; off; off >>= 1) {
            acc[j].x += __shfl_down_sync(0xffffffffu, acc[j].x, off);
            acc[j].y += __shfl_down_sync(0xffffffffu, acc[j].y, off);
        }
    __shared__ float2 red[4][M1*M2];
    int w = t >> 5, lane = t & 31;
    if (lane == 0) {
        #pragma unroll
        for (int j = 0; j < M1*M2; j++) red[w][j] = acc[j];
    }
    __syncthreads();
    if (t < M1*M2) {
        float2 s = red[0][t];
        #pragma unroll
        for (int w2 = 1; w2 < 4; w2++) { s.x += red[w2][t].x; s.y += red[w2][t].y; }
        g_res2[bk*M1*M2 + t] = s;
    }
}

// ---------------- G[b,c,k,q,z] = sum_p res2[b,c,p,q] * E1[c,k,p,z] ---------
__global__ void k_G() {
    int blk = blockIdx.x;
    int b = blk >> 10, c = (blk >> 5) & 31, k = blk & 31;
    int z = threadIdx.x;
    __shared__ float2 r2[M1*M2];
    if (z < M1*M2) r2[z] = g_res2[(b*CO + c)*M1*M2 + z];
    __syncthreads();
    float2 e1[M1];
    #pragma unroll
    for (int p = 0; p < M1; p++) e1[p] = g_E1[((c*CO + k)*M1 + p)*NY + z];
    #pragma unroll
    for (int q = 0; q < M2; q++) {
        float2 acc = make_float2(0.f, 0.f);
        #pragma unroll
        for (int p = 0; p < M1; p++) acc = cfma(r2[p*M2 + q], e1[p], acc);
        g_G[(((size_t)(b*CI + c)*CO + k)*M2 + q)*NY + z] = acc;
    }
}

// ---------------- x2: out += Re( G[z,cq] * E2[cq,x] ) / (NY*NX) ------------
// 2 blocks per (b,k): z split. 128 threads, 8x8 real tiles.
__global__ void __launch_bounds__(128, 4) k_x2(float* __restrict__ out) {
    __shared__ float2 Gs[16][65];         // [k-chunk][z(64)]
    __shared__ float2 Es[16][129];        // [k-chunk][x(128)]
    int blk = blockIdx.x;
    int zh  = blk & 1;
    int bk  = blk >> 1;
    int b = bk >> 5, k = bk & 31;
    int z0 = zh * 64;
    int t = threadIdx.x;
    int u = t >> 4;                       // z-group 0..7 (tile 8)
    int v = t & 15;                       // x-group 0..15 (tile 8)
    float acc[8][8];
    #pragma unroll
    for (int j = 0; j < 8; j++)
        #pragma unroll
        for (int jj = 0; jj < 8; jj++) acc[j][jj] = 0.f;
    for (int k0 = 0; k0 < CI*M2; k0 += 16) {
        __syncthreads();
        for (int l = t; l < 16*64; l += 128) {
            int r = l >> 6, zz = l & 63;
            int cq = k0 + r; int c = cq / M2, q = cq % M2;
            Gs[r][zz] = g_G[(((size_t)(b*CI + c)*CO + k)*M2 + q)*NY + z0 + zz];
        }
        for (int l = t; l < 16*128; l += 128) {
            int r = l >> 7, xx = l & 127;
            int cq = k0 + r; int c = cq / M2, q = cq % M2;
            Es[r][xx] = g_E2[((size_t)(c*CO + k)*M2 + q)*NX + xx];
        }
        __syncthreads();
        #pragma unroll
        for (int kk = 0; kk < 16; kk++) {
            float2 gr[8], er[8];
            #pragma unroll
            for (int j = 0; j < 8; j++)  gr[j]  = Gs[kk][u*8 + j];
            #pragma unroll
            for (int jj = 0; jj < 8; jj++) er[jj] = Es[kk][v + 16*jj];
            #pragma unroll
            for (int j = 0; j < 8; j++)
                #pragma unroll
                for (int jj = 0; jj < 8; jj++)
                    acc[j][jj] = fmaf(gr[j].x, er[jj].x,
                                 fmaf(-gr[j].y, er[jj].y, acc[j][jj]));
        }
    }
    const float INV = 1.0f / (float)(NY * NX);
    float* ob = out + (size_t)(b*CO + k) * NY * NX;
    #pragma unroll
    for (int j = 0; j < 8; j++) {
        int z = z0 + u*8 + j;
        #pragma unroll
        for (int jj = 0; jj < 8; jj++)
            ob[(size_t)z * NX + v + 16*jj] += acc[j][jj] * INV;
    }
}

// ---------------------------------------------------------------------------
extern "C" void kernel_launch(void* const* d_in, const int* in_sizes, int n_in,
                              void* d_out, int out_size) {
    const float* x      = (const float*)d_in[0];
    const float* wp1_re = (const float*)d_in[1];
    const float* wp1_im = (const float*)d_in[2];
    const float* wp2_re = (const float*)d_in[3];
    const float* wp2_im = (const float*)d_in[4];
    const float* wr_re  = (const float*)d_in[5];
    const float* wr_im  = (const float*)d_in[6];
    const float* ty     = (const float*)d_in[7];
    const float* tx     = (const float*)d_in[8];
    float* out = (float*)d_out;

    cudaFuncSetAttribute(k_T2, cudaFuncAttributeMaxDynamicSharedMemorySize, (int)T2_SMEM);

    k_tw          <<<1, 64>>>();
    k_fft_rows_f  <<<B*CI*NY/2, 128>>>(x);
    k_fft_cols_f  <<<B*CI*8, 128>>>();
    k_fac         <<<CI*CO*(M1+M2), 128>>>(wp1_re, wp1_im, wp2_re, wp2_im, ty, tx);
    // pole-residue path first (alpha is L2-hot, H traffic comes later)
    k_T2          <<<B*CI, 128, T2_SMEM>>>();
    k_res2        <<<B*CO, 128>>>(wr_re, wr_im);
    k_G           <<<B*CI*CO, 128>>>();
    // frequency-domain mixing path
    k_hsum        <<<CI*CO, 128>>>(wr_re, wr_im);
    k_res1        <<<(CO/4)*NY, 128>>>();
    k_ifft_rows_f <<<B*CO*NY/2, 128>>>();
    k_ifft_cols_r <<<B*CO*8, 128>>>(out);
    k_x2          <<<B*CO*2, 128>>>(out);
}